// round 13
// baseline (speedup 1.0000x reference)
#include <cuda_runtime.h>
#include <cuda_fp16.h>
#include <math.h>

// dims: VOCAB=32000 E=256 U=512 4U=2048 T=512 B=128
// LSTM: 8 groups x 16 CTAs; CTA = 16 batch x 128 gate cols (32 units)
// Frag-permuted gate cols (epilogue in regs). Per-CTA release flags +
// 4-chunk overlapped h consumption (poll -> cp.async -> mma per 128-unit chunk).

__device__ __align__(16) __half g_embW[32000u * 2048u];  // emb@Wx+b, frag-permuted cols
__device__ __align__(16) __half g_embh[32000u * 256u];   // emb fp16
__device__ __align__(16) __half g_Wxr[256 * 2048];       // Wx frag-permuted fp16
__device__ __align__(16) __half g_Whr[512 * 2048];       // Wh frag-permuted fp16
__device__ __align__(16) float  g_br[2048];
__device__ __align__(16) __half g_hbuf[2 * 128 * 512];   // double-buffered h
__device__ unsigned g_flag[128 * 32];                    // per-CTA flags, 128B apart

static __device__ __forceinline__ unsigned su(const void* p) {
    return (unsigned)__cvta_generic_to_shared(p);
}
static __device__ __forceinline__ void ldsm4(unsigned* r, unsigned a) {
    asm volatile("ldmatrix.sync.aligned.m8n8.x4.shared.b16 {%0,%1,%2,%3}, [%4];\n"
        : "=r"(r[0]), "=r"(r[1]), "=r"(r[2]), "=r"(r[3]) : "r"(a));
}
static __device__ __forceinline__ void ldsm4t(unsigned* r, unsigned a) {
    asm volatile("ldmatrix.sync.aligned.m8n8.x4.trans.shared.b16 {%0,%1,%2,%3}, [%4];\n"
        : "=r"(r[0]), "=r"(r[1]), "=r"(r[2]), "=r"(r[3]) : "r"(a));
}
static __device__ __forceinline__ void mmaf(float* d, const unsigned* a, const unsigned* b) {
    asm volatile("mma.sync.aligned.m16n8k16.row.col.f32.f16.f16.f32 "
        "{%0,%1,%2,%3}, {%4,%5,%6,%7}, {%8,%9}, {%0,%1,%2,%3};\n"
        : "+f"(d[0]), "+f"(d[1]), "+f"(d[2]), "+f"(d[3])
        : "r"(a[0]), "r"(a[1]), "r"(a[2]), "r"(a[3]), "r"(b[0]), "r"(b[1]));
}
static __device__ __forceinline__ float tanh_ap(float x) {
    float r; asm("tanh.approx.f32 %0, %1;" : "=f"(r) : "f"(x)); return r;
}
static __device__ __forceinline__ float sig_ap(float x) {
    return fmaf(tanh_ap(0.5f * x), 0.5f, 0.5f);
}
#define CPA(dst, src) asm volatile("cp.async.ca.shared.global [%0], [%1], 16;\n" :: "r"(dst), "l"(src))
#define CPG(dst, src) asm volatile("cp.async.cg.shared.global [%0], [%1], 16;\n" :: "r"(dst), "l"(src))

// ---------- prep: fragment-permute weights to fp16, convert emb, zero state ----------
__global__ void prep_kernel(const float* __restrict__ emb, const float* __restrict__ Wx,
                            const float* __restrict__ Wh, const float* __restrict__ b) {
    int tid = blockIdx.x * blockDim.x + threadIdx.x, nth = gridDim.x * blockDim.x;
    for (int i = tid; i < 32000 * 128; i += nth) {
        float2 v = *(const float2*)(emb + (size_t)i * 2);
        *(__half2*)(g_embh + (size_t)i * 2) = __floats2half2_rn(v.x, v.y);
    }
    // permuted col p -> (gate, unit): m=p>>7, r=p&127, w=r>>4, t2=r&15
    // gate = (t2>>3)*2 + (t2&1), s=(t2&7)>>1, unit = m*32 + w*4 + s
    for (int i = tid; i < 256 * 2048; i += nth) {
        int k = i >> 11, p = i & 2047;
        int m = p >> 7, r = p & 127, w = r >> 4, t2 = r & 15;
        int gate = (t2 >> 3) * 2 + (t2 & 1), s = (t2 & 7) >> 1;
        g_Wxr[i] = __float2half_rn(Wx[k * 2048 + gate * 512 + m * 32 + w * 4 + s]);
    }
    for (int i = tid; i < 512 * 2048; i += nth) {
        int k = i >> 11, p = i & 2047;
        int m = p >> 7, r = p & 127, w = r >> 4, t2 = r & 15;
        int gate = (t2 >> 3) * 2 + (t2 & 1), s = (t2 & 7) >> 1;
        g_Whr[i] = __float2half_rn(Wh[k * 2048 + gate * 512 + m * 32 + w * 4 + s]);
    }
    for (int i = tid; i < 2048; i += nth) {
        int m = i >> 7, r = i & 127, w = r >> 4, t2 = r & 15;
        int gate = (t2 >> 3) * 2 + (t2 & 1), s = (t2 & 7) >> 1;
        g_br[i] = b[gate * 512 + m * 32 + w * 4 + s];
    }
    for (int i = tid; i < 2 * 128 * 512; i += nth) g_hbuf[i] = __float2half_rn(0.f);
    for (int i = tid; i < 128 * 32; i += nth) g_flag[i] = 0u;
}

// ---------- embW = embh @ Wxr + br : CTA 128x128, K=256, cp.async double-buffered ----------
__global__ __launch_bounds__(256) void embw_gemm() {
    __shared__ __align__(16) __half As[2][128 * 40];
    __shared__ __align__(16) __half Bs[2][32 * 136];
    int tid = threadIdx.x, lane = tid & 31, w = tid >> 5, wm = w >> 2, wn = w & 3;
    int m0 = blockIdx.y * 128, n0 = blockIdx.x * 128;
    float acc[4][4][4];
    #pragma unroll
    for (int i = 0; i < 4; i++)
        #pragma unroll
        for (int j = 0; j < 4; j++)
            #pragma unroll
            for (int k = 0; k < 4; k++) acc[i][j][k] = 0.f;
    int q = lane >> 3, l7 = lane & 7;
    auto issue = [&](int kt, int buf) {
        int k0 = kt * 32;
        unsigned sAb = su(As[buf]), sBb = su(Bs[buf]);
        #pragma unroll
        for (int i = 0; i < 2; i++) {
            int idx = tid + i * 256; int r = idx >> 2, cc = (idx & 3) * 8;
            CPA(sAb + (unsigned)((r * 40 + cc) * 2), g_embh + (size_t)(m0 + r) * 256 + k0 + cc);
        }
        #pragma unroll
        for (int i = 0; i < 2; i++) {
            int idx = tid + i * 256; int r = idx >> 4, cc = (idx & 15) * 8;
            CPA(sBb + (unsigned)((r * 136 + cc) * 2), g_Wxr + (size_t)(k0 + r) * 2048 + n0 + cc);
        }
        asm volatile("cp.async.commit_group;\n");
    };
    issue(0, 0);
    for (int kt = 0; kt < 8; kt++) {
        int buf = kt & 1;
        if (kt < 7) { issue(kt + 1, buf ^ 1); asm volatile("cp.async.wait_group 1;\n"); }
        else        { asm volatile("cp.async.wait_group 0;\n"); }
        __syncthreads();
        unsigned sA = su(As[buf]), sB = su(Bs[buf]);
        #pragma unroll
        for (int ks = 0; ks < 2; ks++) {
            unsigned a[4][4], bb[2][4];
            #pragma unroll
            for (int mt = 0; mt < 4; mt++) {
                int r = wm * 64 + mt * 16 + (q & 1) * 8 + l7, c = ks * 16 + (q >> 1) * 8;
                ldsm4(a[mt], sA + (unsigned)((r * 40 + c) * 2));
            }
            #pragma unroll
            for (int n2 = 0; n2 < 2; n2++) {
                int r = ks * 16 + (q & 1) * 8 + l7, c = wn * 32 + n2 * 16 + (q >> 1) * 8;
                ldsm4t(bb[n2], sB + (unsigned)((r * 136 + c) * 2));
            }
            #pragma unroll
            for (int mt = 0; mt < 4; mt++) {
                mmaf(acc[mt][0], a[mt], bb[0]); mmaf(acc[mt][1], a[mt], bb[0] + 2);
                mmaf(acc[mt][2], a[mt], bb[1]); mmaf(acc[mt][3], a[mt], bb[1] + 2);
            }
        }
        __syncthreads();
    }
    #pragma unroll
    for (int mt = 0; mt < 4; mt++)
        #pragma unroll
        for (int nt = 0; nt < 4; nt++) {
            int r = m0 + wm * 64 + mt * 16 + (lane >> 2);
            int c = n0 + wn * 32 + nt * 8 + (lane & 3) * 2;
            float2 bv = *(const float2*)(g_br + c);
            *(__half2*)(g_embW + (size_t)r * 2048 + c) =
                __floats2half2_rn(acc[mt][nt][0] + bv.x, acc[mt][nt][1] + bv.y);
            *(__half2*)(g_embW + (size_t)(r + 8) * 2048 + c) =
                __floats2half2_rn(acc[mt][nt][2] + bv.x, acc[mt][nt][3] + bv.y);
        }
}

// ---------- recurrence: persistent 128 CTAs, chunked overlapped exchange ----------
#define OFF_HS 139264
#define LSTM_SMEM (OFF_HS + 16 * 1040)

__global__ __launch_bounds__(256, 1) void lstm_kernel(const int* __restrict__ sentence) {
    extern __shared__ __align__(16) char smem[];
    __half* whs = (__half*)smem;
    int tid = threadIdx.x, lane = tid & 31, w = tid >> 5;
    int g = blockIdx.x >> 4, m = blockIdx.x & 15;
    int q = lane >> 3, l7 = lane & 7;

    #pragma unroll 4
    for (int i = 0; i < 32; i++) {
        int idx = tid + i * 256; int k = idx >> 4, c = (idx & 15) * 8;
        *(uint4*)(whs + k * 136 + c) = *(const uint4*)(g_Whr + (size_t)k * 2048 + m * 128 + c);
    }
    __syncthreads();

    // Wh B-fragments -> registers (time-invariant)
    unsigned Bf[32][4];
    {
        unsigned sW = su(whs);
        #pragma unroll
        for (int kk = 0; kk < 32; kk++) {
            int r = kk * 16 + (q & 1) * 8 + l7, c = w * 16 + (q >> 1) * 8;
            ldsm4t(Bf[kk], sW + (unsigned)((r * 136 + c) * 2));
        }
    }
    const unsigned sH = su(smem + OFF_HS);
    const int b0 = lane >> 2, b1 = b0 + 8;
    const int sb0 = (g * 16 + b0) * 512, sb1 = (g * 16 + b1) * 512;
    const int xcol = m * 128 + w * 16 + (lane & 3) * 2;
    const int ug = m * 32 + w * 4 + (lane & 3);
    const int hr = tid >> 4, hsl = tid & 15;          // h-chunk staging: row, 16B slot
    unsigned* myflag = &g_flag[(g * 16 + m) * 32];
    const unsigned* grpflags = &g_flag[g * 16 * 32];
    float cst0 = 0.f, cst1 = 0.f;

    unsigned xc[4];
    {
        const __half* p0 = g_embW + (size_t)sentence[sb0] * 2048 + xcol;
        const __half* p1 = g_embW + (size_t)sentence[sb1] * 2048 + xcol;
        xc[0] = *(const unsigned*)p0; xc[1] = *(const unsigned*)(p0 + 8);
        xc[2] = *(const unsigned*)p1; xc[3] = *(const unsigned*)(p1 + 8);
    }

    for (int t = 0; t < 512; t++) {
        // prefetch x(t+1) first (long-latency, fully overlapped)
        unsigned xn[4];
        {
            int tn = (t + 1 < 512) ? t + 1 : 511;
            const __half* p0 = g_embW + (size_t)sentence[sb0 + tn] * 2048 + xcol;
            const __half* p1 = g_embW + (size_t)sentence[sb1 + tn] * 2048 + xcol;
            xn[0] = *(const unsigned*)p0; xn[1] = *(const unsigned*)(p0 + 8);
            xn[2] = *(const unsigned*)p1; xn[3] = *(const unsigned*)(p1 + 8);
        }
        const __half* hsrc = g_hbuf + (size_t)(t & 1) * 65536 + (size_t)g * 16 * 512;
        // issue 4 chunks: poll the 4 producer CTAs of each 128-unit chunk, then cp.async
        #pragma unroll
        for (int j = 0; j < 4; j++) {
            if (t && lane < 4) {
                const unsigned* fl = grpflags + (j * 4 + lane) * 32;
                unsigned v;
                do { asm volatile("ld.acquire.gpu.global.u32 %0, [%1];" : "=r"(v) : "l"(fl)); }
                while (v < (unsigned)t);
            }
            __syncwarp();
            CPG(sH + (unsigned)(hr * 1040 + (j * 16 + hsl) * 16),
                hsrc + hr * 512 + j * 128 + hsl * 8);
            asm volatile("cp.async.commit_group;\n");
        }
        // consume chunks with progressive waits (fetch j+1.. overlaps mma of j)
        float acc[2][4] = {};
        #pragma unroll
        for (int j = 0; j < 4; j++) {
            if (j == 0)      asm volatile("cp.async.wait_group 3;\n");
            else if (j == 1) asm volatile("cp.async.wait_group 2;\n");
            else if (j == 2) asm volatile("cp.async.wait_group 1;\n");
            else             asm volatile("cp.async.wait_group 0;\n");
            __syncthreads();
            #pragma unroll
            for (int kk = j * 8; kk < j * 8 + 8; kk++) {
                unsigned a[4];
                int r = (q & 1) * 8 + l7, c = kk * 16 + (q >> 1) * 8;
                ldsm4(a, sH + (unsigned)(r * 1040 + c * 2));
                mmaf(acc[0], a, Bf[kk]); mmaf(acc[1], a, Bf[kk] + 2);
            }
        }
        // epilogue in registers
        {
            float2 xa = __half22float2(*(__half2*)&xc[0]);
            float2 xb = __half22float2(*(__half2*)&xc[1]);
            float zi = acc[0][0] + xa.x, zf = acc[0][1] + xa.y;
            float zg = acc[1][0] + xb.x, zo = acc[1][1] + xb.y;
            cst0 = sig_ap(zf) * cst0 + sig_ap(zi) * tanh_ap(zg);
            float h0 = sig_ap(zo) * tanh_ap(cst0);
            xa = __half22float2(*(__half2*)&xc[2]);
            xb = __half22float2(*(__half2*)&xc[3]);
            zi = acc[0][2] + xa.x; zf = acc[0][3] + xa.y;
            zg = acc[1][2] + xb.x; zo = acc[1][3] + xb.y;
            cst1 = sig_ap(zf) * cst1 + sig_ap(zi) * tanh_ap(zg);
            float h1 = sig_ap(zo) * tanh_ap(cst1);
            __half* hdst = g_hbuf + (size_t)((t + 1) & 1) * 65536;
            unsigned short u0 = __half_as_ushort(__float2half_rn(h0));
            unsigned short u1 = __half_as_ushort(__float2half_rn(h1));
            asm volatile("st.global.cg.u16 [%0], %1;" :: "l"(hdst + sb0 + ug), "h"(u0) : "memory");
            asm volatile("st.global.cg.u16 [%0], %1;" :: "l"(hdst + sb1 + ug), "h"(u1) : "memory");
        }
        xc[0] = xn[0]; xc[1] = xn[1]; xc[2] = xn[2]; xc[3] = xn[3];
        __syncthreads();
        if (tid == 0)
            asm volatile("st.release.gpu.global.u32 [%0], %1;" :: "l"(myflag), "r"((unsigned)(t + 1)) : "memory");
    }
}

// ---------- MLP head: one block per batch row ----------
// h(512) lives in buffer (512)&1 == 0 -> read g_hbuf + 0.
__global__ void mlp_kernel(const float* __restrict__ W1, const float* __restrict__ b1,
                           const float* __restrict__ W2, const float* __restrict__ b2,
                           const float* __restrict__ W3, const float* __restrict__ b3,
                           float* __restrict__ out) {
    __shared__ float hr[512], h1[128], h2[64];
    int b = blockIdx.x, tid = threadIdx.x;
    #pragma unroll
    for (int i = 0; i < 4; i++)
        hr[tid + i * 128] = __half2float(g_hbuf[(size_t)b * 512 + tid + i * 128]);
    __syncthreads();
    float a0 = 0.f, a1 = 0.f, a2 = 0.f, a3 = 0.f;
    #pragma unroll 2
    for (int k = 0; k < 512; k += 4) {
        a0 = fmaf(hr[k],     W1[k * 128 + tid],       a0);
        a1 = fmaf(hr[k + 1], W1[(k + 1) * 128 + tid], a1);
        a2 = fmaf(hr[k + 2], W1[(k + 2) * 128 + tid], a2);
        a3 = fmaf(hr[k + 3], W1[(k + 3) * 128 + tid], a3);
    }
    h1[tid] = fmaxf(b1[tid] + (a0 + a1) + (a2 + a3), 0.f);
    __syncthreads();
    if (tid < 64) {
        float s0 = 0.f, s1 = 0.f;
        for (int k = 0; k < 128; k += 2) {
            s0 = fmaf(h1[k],     W2[k * 64 + tid],       s0);
            s1 = fmaf(h1[k + 1], W2[(k + 1) * 64 + tid], s1);
        }
        h2[tid] = fmaxf(b2[tid] + s0 + s1, 0.f);
    }
    __syncthreads();
    if (tid == 0) {
        float a3s = b3[0];
        for (int k = 0; k < 64; k++) a3s = fmaf(h2[k], W3[k], a3s);
        out[b] = 1.f / (1.f + __expf(-a3s));
    }
}

extern "C" void kernel_launch(void* const* d_in, const int* in_sizes, int n_in,
                              void* d_out, int out_size) {
    const int*   sentence = (const int*)d_in[0];
    const float* emb = (const float*)d_in[1];
    const float* Wx  = (const float*)d_in[2];
    const float* Wh  = (const float*)d_in[3];
    const float* b   = (const float*)d_in[4];
    const float* W1  = (const float*)d_in[5];
    const float* b1  = (const float*)d_in[6];
    const float* W2  = (const float*)d_in[7];
    const float* b2  = (const float*)d_in[8];
    const float* W3  = (const float*)d_in[9];
    const float* b3  = (const float*)d_in[10];
    float* out = (float*)d_out;
    cudaFuncSetAttribute(lstm_kernel, cudaFuncAttributeMaxDynamicSharedMemorySize, LSTM_SMEM);
    prep_kernel<<<512, 256>>>(emb, Wx, Wh, b);
    embw_gemm<<<dim3(16, 250), 256>>>();
    lstm_kernel<<<128, 256, LSTM_SMEM>>>(sentence);
    mlp_kernel<<<128, 128>>>(W1, b1, W2, b2, W3, b3, out);
}